// round 2
// baseline (speedup 1.0000x reference)
#include <cuda_runtime.h>

#define SELU_SCALE 1.0507009873554804934193349852946f
#define SELU_ALPHA 1.6732632423543772848170429916717f

// Each thread processes 8 points. All global traffic is float4/int4 coalesced,
// with streaming (evict-first) cache hints since every byte is touched once.
__global__ __launch_bounds__(256) void ifs_kernel(
    const float4* __restrict__ pts,      // points: 6 float4 per 8 points
    const float4* __restrict__ pcol,     // prev_colors likewise
    const int4*   __restrict__ chs,      // choices: 2 int4 per 8 points
    const float*  __restrict__ matrices, // [K,3,3] = 72 floats
    const float*  __restrict__ biases,   // [K,3]   = 24 floats
    const float*  __restrict__ colors,   // [K,3]   = 24 floats
    float4* __restrict__ out_tp,         // tp output, 6 float4 per 8 points
    float4* __restrict__ out_col,        // new_colors output
    int nocts)                           // N/8
{
    __shared__ float sM[72];
    __shared__ float sB[24];
    __shared__ float sC[24];
    {
        int t = threadIdx.x;
        if (t < 72) sM[t] = matrices[t];
        if (t < 24) sB[t] = biases[t];
        else if (t >= 32 && t < 56) sC[t - 32] = colors[t - 32];
    }
    __syncthreads();

    int i = blockIdx.x * blockDim.x + threadIdx.x;
    if (i >= nocts) return;

    // Front-batch ALL loads (13 independent LDG.128 in flight per thread).
    float4 p[6], c[6];
    int4 ch0, ch1;
#pragma unroll
    for (int q = 0; q < 6; q++) p[q] = __ldcs(&pts[6 * i + q]);
#pragma unroll
    for (int q = 0; q < 6; q++) c[q] = __ldcs(&pcol[6 * i + q]);
    ch0 = __ldcs(&chs[2 * i + 0]);
    ch1 = __ldcs(&chs[2 * i + 1]);

    // Flatten to scalar views
    const float* pf = (const float*)p;   // 24 floats = 8 points x 3
    const float* cf = (const float*)c;
    int cc[8] = {ch0.x, ch0.y, ch0.z, ch0.w, ch1.x, ch1.y, ch1.z, ch1.w};

    float tp[24];
    float nc[24];

#pragma unroll
    for (int j = 0; j < 8; j++) {
        int sel = cc[j];
        const float* M = sM + sel * 9;
        const float* B = sB + sel * 3;
        const float* C = sC + sel * 3;
        float x = pf[3 * j + 0], y = pf[3 * j + 1], z = pf[3 * j + 2];
#pragma unroll
        for (int e = 0; e < 3; e++) {
            // tp[e] = sum_d p[d] * M[d][e] + b[e]  (contract over FIRST matrix axis)
            float v = fmaf(x, M[0 * 3 + e], fmaf(y, M[1 * 3 + e], fmaf(z, M[2 * 3 + e], B[e])));
            float neg = SELU_SCALE * SELU_ALPHA * (__expf(v) - 1.0f);
            float pos = SELU_SCALE * v;
            tp[3 * j + e] = v > 0.0f ? pos : neg;
            nc[3 * j + e] = (cf[3 * j + e] + C[e]) * 0.5f;
        }
    }

    const float4* tpv = (const float4*)tp;
    const float4* ncv = (const float4*)nc;
#pragma unroll
    for (int q = 0; q < 6; q++) __stcs(&out_tp[6 * i + q], tpv[q]);
#pragma unroll
    for (int q = 0; q < 6; q++) __stcs(&out_col[6 * i + q], ncv[q]);
}

extern "C" void kernel_launch(void* const* d_in, const int* in_sizes, int n_in,
                              void* d_out, int out_size)
{
    const float4* pts      = (const float4*)d_in[0];  // points      [N,3] f32
    const float4* pcol     = (const float4*)d_in[1];  // prev_colors [N,3] f32
    const int4*   chs      = (const int4*)d_in[2];    // choices     [N]   i32
    const float*  matrices = (const float*)d_in[3];   // [K,3,3]
    const float*  biases   = (const float*)d_in[4];   // [K,3]
    const float*  colors   = (const float*)d_in[5];   // [K,3]

    int N = in_sizes[2];          // choices element count == N
    int nocts = N / 8;

    float* out = (float*)d_out;
    float4* out_tp  = (float4*)out;                    // first N*3 floats: tp
    float4* out_col = (float4*)(out + (size_t)N * 3);  // next N*3 floats: new_colors

    int threads = 256;
    int blocks = (nocts + threads - 1) / threads;
    ifs_kernel<<<blocks, threads>>>(pts, pcol, chs, matrices, biases, colors,
                                    out_tp, out_col, nocts);
}

// round 5
// speedup vs baseline: 1.5891x; 1.5891x over previous
#include <cuda_runtime.h>

#define SELU_SCALE 1.0507009873554804934193349852946f
#define SELU_ALPHA 1.6732632423543772848170429916717f

// Each thread processes 4 points. All global traffic is float4/int4 coalesced,
// with streaming (evict-first) hints: every byte is touched exactly once.
// Per-thread data kept as named float4 components (no pointer-cast local views,
// which spill to local memory on this compiler — R2 post-mortem).
__global__ __launch_bounds__(256) void ifs_kernel(
    const float4* __restrict__ pts,      // points as float4: 3 float4 per 4 points
    const float4* __restrict__ pcol,     // prev_colors likewise
    const int4*   __restrict__ chs,      // choices: 1 int4 per 4 points
    const float*  __restrict__ matrices, // [K,3,3] = 72 floats
    const float*  __restrict__ biases,   // [K,3]   = 24 floats
    const float*  __restrict__ colors,   // [K,3]   = 24 floats
    float4* __restrict__ out_tp,         // tp output, 3 float4 per 4 points
    float4* __restrict__ out_col,        // new_colors output
    int nquads)                          // N/4
{
    __shared__ float sM[72];
    __shared__ float sB[24];
    __shared__ float sC[24];
    {
        int t = threadIdx.x;
        if (t < 72) sM[t] = matrices[t];
        if (t < 24) sB[t] = biases[t];
        else if (t >= 32 && t < 56) sC[t - 32] = colors[t - 32];
    }
    __syncthreads();

    int i = blockIdx.x * blockDim.x + threadIdx.x;
    if (i >= nquads) return;

    float4 p0 = __ldcs(&pts[3 * i + 0]);
    float4 p1 = __ldcs(&pts[3 * i + 1]);
    float4 p2 = __ldcs(&pts[3 * i + 2]);
    float4 c0 = __ldcs(&pcol[3 * i + 0]);
    float4 c1 = __ldcs(&pcol[3 * i + 1]);
    float4 c2 = __ldcs(&pcol[3 * i + 2]);
    int4   ch = __ldcs(&chs[i]);

    float px[4][3] = {
        {p0.x, p0.y, p0.z},
        {p0.w, p1.x, p1.y},
        {p1.z, p1.w, p2.x},
        {p2.y, p2.z, p2.w}
    };
    float pc[4][3] = {
        {c0.x, c0.y, c0.z},
        {c0.w, c1.x, c1.y},
        {c1.z, c1.w, c2.x},
        {c2.y, c2.z, c2.w}
    };
    int cc[4] = {ch.x, ch.y, ch.z, ch.w};

    float tp[4][3];
    float nc[4][3];

#pragma unroll
    for (int j = 0; j < 4; j++) {
        int c = cc[j];
        const float* M = sM + c * 9;
        const float* B = sB + c * 3;
        const float* C = sC + c * 3;
        float x = px[j][0], y = px[j][1], z = px[j][2];
#pragma unroll
        for (int e = 0; e < 3; e++) {
            // tp[e] = sum_d p[d] * M[d][e] + b[e]  (contract over FIRST matrix axis)
            float v = fmaf(x, M[0 * 3 + e], fmaf(y, M[1 * 3 + e], fmaf(z, M[2 * 3 + e], B[e])));
            float neg = SELU_SCALE * SELU_ALPHA * (__expf(v) - 1.0f);
            float pos = SELU_SCALE * v;
            tp[j][e] = v > 0.0f ? pos : neg;
            nc[j][e] = (pc[j][e] + C[e]) * 0.5f;
        }
    }

    __stcs(&out_tp[3 * i + 0], make_float4(tp[0][0], tp[0][1], tp[0][2], tp[1][0]));
    __stcs(&out_tp[3 * i + 1], make_float4(tp[1][1], tp[1][2], tp[2][0], tp[2][1]));
    __stcs(&out_tp[3 * i + 2], make_float4(tp[2][2], tp[3][0], tp[3][1], tp[3][2]));

    __stcs(&out_col[3 * i + 0], make_float4(nc[0][0], nc[0][1], nc[0][2], nc[1][0]));
    __stcs(&out_col[3 * i + 1], make_float4(nc[1][1], nc[1][2], nc[2][0], nc[2][1]));
    __stcs(&out_col[3 * i + 2], make_float4(nc[2][2], nc[3][0], nc[3][1], nc[3][2]));
}

extern "C" void kernel_launch(void* const* d_in, const int* in_sizes, int n_in,
                              void* d_out, int out_size)
{
    const float4* pts      = (const float4*)d_in[0];  // points      [N,3] f32
    const float4* pcol     = (const float4*)d_in[1];  // prev_colors [N,3] f32
    const int4*   chs      = (const int4*)d_in[2];    // choices     [N]   i32
    const float*  matrices = (const float*)d_in[3];   // [K,3,3]
    const float*  biases   = (const float*)d_in[4];   // [K,3]
    const float*  colors   = (const float*)d_in[5];   // [K,3]

    int N = in_sizes[2];          // choices element count == N
    int nquads = N / 4;

    float* out = (float*)d_out;
    float4* out_tp  = (float4*)out;                    // first N*3 floats: tp
    float4* out_col = (float4*)(out + (size_t)N * 3);  // next N*3 floats: new_colors

    int threads = 256;
    int blocks = (nquads + threads - 1) / threads;
    ifs_kernel<<<blocks, threads>>>(pts, pcol, chs, matrices, biases, colors,
                                    out_tp, out_col, nquads);
}